// round 16
// baseline (speedup 1.0000x reference)
#include <cuda_runtime.h>
#include <cuda_bf16.h>
#include <math.h>

// Problem shape (fixed by dataset): X [2048,16,32,32] f32, weight [32,32] f32.
#define NM      32768          // 2048*16 matrices
#define NEL     1024           // 32*32
#define LM_WPB  8              // warps (matrices) per block in heavy kernels
#define LM_BLOCKS (NM / LM_WPB)  // 4096

// per-warp region in k_logmean (floats): sA33[1056] | sP[1024] | sCS2[32] | sLam[32]
#define LM_WARP_FLOATS 2144
#define LM_SMEM_FLOATS (1024 + LM_WPB * LM_WARP_FLOATS)   // gis_p + 8 warps

// ---------------- device scratch (static, no allocation) ----------------
__device__ float d_partA[256 * NEL];        // stage-A block partials
__device__ float d_g0[NEL];                 // arithmetic mean of X
__device__ float d_gs[NEL];                 // sqrtm(g0)
__device__ float d_gis[NEL];                // invsqrtm(g0)
__device__ float d_ws[NEL];                 // sqrtm(weight)
__device__ float d_partT[LM_BLOCKS * NEL];  // per-block logm partial sums (16 MB)
__device__ float d_partT2[64 * NEL];        // second-level partials
__device__ float d_t[NEL];                  // mean of logms
__device__ float d_Af[NEL];                 // final congruence factor ws*gis2

// ---------------- small helpers ----------------
__device__ __forceinline__ void get_pq(int r, int k, int& p, int& q) {
    if (k == 0) { p = 31; q = r; }
    else {
        p = r + k; if (p >= 31) p -= 31;
        q = r - k; if (q < 0)  q += 31;
    }
}

// Compute the 16 disjoint rotations for round r (lanes 0-15), store (c,s)
// pairs as float2. Branchless: skip folds to (1,0), bitwise-identical update.
__device__ __forceinline__ void jacobi_phase1(const float* sA, float2* sCS2,
                                              int lane, int r, float skip,
                                              float& off) {
    if (lane < 16) {
        int p, q; get_pq(r, lane, p, q);
        float app = sA[p * 33 + p];
        float aqq = sA[q * 33 + q];
        float apq = sA[p * 33 + q];
        off += apq * apq;
        bool g = fabsf(apq) > skip * (fabsf(app) + fabsf(aqq) + 1e-30f);
        float den = g ? apq : 1.0f;
        float theta = 0.5f * (aqq - app) / den;
        float tt = 1.0f / (fabsf(theta) + sqrtf(1.0f + theta * theta));
        tt = copysignf(tt, theta);
        float c = rsqrtf(1.0f + tt * tt);
        float s = tt * c;
        sCS2[lane] = make_float2(g ? c : 1.0f, g ? s : 0.0f);
    }
}

// =====================================================================
// Smem-based Jacobi (mean-path kernels: k_prep / k_final). Unchanged.
// =====================================================================
__device__ void warp_eigh32(float* sA, float* sV, float2* sCS2, int lane,
                            float tol, float skip) {
    float* rowA = sA + lane * 33;
    float* rowV = sV + lane * 33;
    float* colA = sA + lane;

    #pragma unroll
    for (int i = 0; i < 32; i++) rowV[i] = (i == lane) ? 1.0f : 0.0f;
    __syncwarp();

    #pragma unroll 1
    for (int sweep = 0; sweep < 10; sweep++) {
        float off = 0.0f;
        #pragma unroll 1
        for (int r = 0; r < 31; r++) {
            jacobi_phase1(sA, sCS2, lane, r, skip, off);
            __syncwarp();
            #pragma unroll
            for (int k = 0; k < 16; k++) {
                float2 cs = sCS2[k];
                int p, q; get_pq(r, k, p, q);
                float x = rowA[p], y = rowA[q];
                rowA[p] = cs.x * x - cs.y * y;
                rowA[q] = cs.y * x + cs.x * y;
                float vx = rowV[p], vy = rowV[q];
                rowV[p] = cs.x * vx - cs.y * vy;
                rowV[q] = cs.y * vx + cs.x * vy;
            }
            __syncwarp();
            #pragma unroll
            for (int k = 0; k < 16; k++) {
                float2 cs = sCS2[k];
                int p, q; get_pq(r, k, p, q);
                float x = colA[p * 33], y = colA[q * 33];
                colA[p * 33] = cs.x * x - cs.y * y;
                colA[q * 33] = cs.y * x + cs.x * y;
            }
            __syncwarp();
        }
        float dd  = rowA[lane];
        float dsq = dd * dd;
        #pragma unroll
        for (int o = 16; o > 0; o >>= 1) {
            off += __shfl_xor_sync(0xffffffffu, off, o);
            dsq += __shfl_xor_sync(0xffffffffu, dsq, o);
        }
        if (off <= tol * dsq) break;
    }
    __syncwarp();
}

// =====================================================================
// Hot-path Jacobi: Brent-Luk seating (V row in registers, static indices,
// rolled loop). On exit writes V TRANSPOSED into packed sVT (stride 32):
// sVT[j*32 + lane] = V[lane][j]  (conflict-free: bank = lane).
// Arithmetic identical to warp_eigh32 -> bitwise-identical results.
// =====================================================================
__device__ void warp_eigh32_bl(float* sA, float* sVT, float2* sCS2, int lane,
                               float tol, float skip) {
    float* rowA = sA + lane * 33;
    float* colA = sA + lane;

    float vp[31], vc;
    #pragma unroll
    for (int j = 0; j < 31; j++) vp[j] = (j == lane) ? 1.0f : 0.0f;
    vc = (lane == 31) ? 1.0f : 0.0f;
    __syncwarp();

    #pragma unroll 1
    for (int sweep = 0; sweep < 10; sweep++) {
        float off = 0.0f;
        #pragma unroll 1
        for (int r = 0; r < 31; r++) {
            jacobi_phase1(sA, sCS2, lane, r, skip, off);
            __syncwarp();
            {   // k = 0: players (31, r) -> registers (vc, vp[0])
                float2 cs = sCS2[0];
                float x = rowA[31], y = rowA[r];
                rowA[31] = cs.x * x - cs.y * y;
                rowA[r]  = cs.y * x + cs.x * y;
                float vx = vc, vy = vp[0];
                vc    = cs.x * vx - cs.y * vy;
                vp[0] = cs.y * vx + cs.x * vy;
            }
            #pragma unroll
            for (int k = 1; k < 16; k++) {
                float2 cs = sCS2[k];
                int p = r + k; if (p >= 31) p -= 31;
                int q = r - k; if (q < 0)  q += 31;
                float x = rowA[p], y = rowA[q];
                rowA[p] = cs.x * x - cs.y * y;
                rowA[q] = cs.y * x + cs.x * y;
                float vx = vp[k], vy = vp[31 - k];
                vp[k]      = cs.x * vx - cs.y * vy;
                vp[31 - k] = cs.y * vx + cs.x * vy;
            }
            __syncwarp();
            {
                float2 cs = sCS2[0];
                float x = colA[31 * 33], y = colA[r * 33];
                colA[31 * 33] = cs.x * x - cs.y * y;
                colA[r * 33]  = cs.y * x + cs.x * y;
            }
            #pragma unroll
            for (int k = 1; k < 16; k++) {
                float2 cs = sCS2[k];
                int p = r + k; if (p >= 31) p -= 31;
                int q = r - k; if (q < 0)  q += 31;
                float x = colA[p * 33], y = colA[q * 33];
                colA[p * 33] = cs.x * x - cs.y * y;
                colA[q * 33] = cs.y * x + cs.x * y;
            }
            __syncwarp();
            // advance seating: player at pos j moves to pos j-1
            float t0 = vp[0];
            #pragma unroll
            for (int j = 0; j < 30; j++) vp[j] = vp[j + 1];
            vp[30] = t0;
        }
        float dd  = rowA[lane];
        float dsq = dd * dd;
        #pragma unroll
        for (int o = 16; o > 0; o >>= 1) {
            off += __shfl_xor_sync(0xffffffffu, off, o);
            dsq += __shfl_xor_sync(0xffffffffu, dsq, o);
        }
        if (off <= tol * dsq) break;
    }
    // sweep boundary: seating is identity -> transposed packed writeback
    #pragma unroll
    for (int j = 0; j < 31; j++) sVT[j * 32 + lane] = vp[j];
    sVT[31 * 32 + lane] = vc;
    __syncwarp();
}

struct FnLog   { __device__ float operator()(float x) const { return logf(fmaxf(x, 1e-30f)); } };
struct FnExp   { __device__ float operator()(float x) const { return expf(x); } };
struct FnSqrt  { __device__ float operator()(float x) const { return sqrtf(fmaxf(x, 0.0f)); } };
struct FnRsqrt { __device__ float operator()(float x) const { return rsqrtf(fmaxf(x, 1e-30f)); } };

// Mean-path matfn (padded sV), unchanged.
template <class F>
__device__ void warp_matfn(const float* sA, const float* sV, float* sTmp,
                           float* out, int ostride, int lane, F f) {
    sTmp[lane] = f(sA[lane * 33 + lane]);
    __syncwarp();
    float vj[32];
    #pragma unroll
    for (int k = 0; k < 32; k++) vj[k] = sV[lane * 33 + k] * sTmp[k];
    __syncwarp();
    #pragma unroll
    for (int i = 0; i < 32; i++) {
        float acc = 0.0f;
        #pragma unroll
        for (int k = 0; k < 32; k++) acc += sV[i * 33 + k] * vj[k];
        out[i * ostride + lane] = acc;
    }
    __syncwarp();
}

// C = A * B (all 32x32, pad-33 smem). C must not alias A or B.
__device__ void warp_mm(float* C, const float* A, const float* B, int lane) {
    float bcol[32];
    #pragma unroll
    for (int l = 0; l < 32; l++) bcol[l] = B[l * 33 + lane];
    #pragma unroll
    for (int i = 0; i < 32; i++) {
        float acc = 0.0f;
        #pragma unroll
        for (int l = 0; l < 32; l++) acc += A[i * 33 + l] * bcol[l];
        C[i * 33 + lane] = acc;
    }
    __syncwarp();
}

// ---------------- stage A: arithmetic mean of all matrices ----------------
__global__ void k_sumA(const float* __restrict__ X) {
    int b = blockIdx.x, t = threadIdx.x;
    const int MPB = NM / 256;   // 128 matrices per block
    const float* base = X + (size_t)b * MPB * NEL;
    float a0 = 0.f, a1 = 0.f, a2 = 0.f, a3 = 0.f;
    for (int m = 0; m < MPB; m++) {
        const float* p = base + (size_t)m * NEL;
        a0 += p[t];        a1 += p[t + 256];
        a2 += p[t + 512];  a3 += p[t + 768];
    }
    d_partA[b * NEL + t]       = a0;
    d_partA[b * NEL + t + 256] = a1;
    d_partA[b * NEL + t + 512] = a2;
    d_partA[b * NEL + t + 768] = a3;
}

__global__ void k_redA() {
    int e = blockIdx.x * 256 + threadIdx.x;
    float s = 0.f;
    #pragma unroll 8
    for (int b = 0; b < 256; b++) s += d_partA[b * NEL + e];
    d_g0[e] = s * (1.0f / (float)NM);
}

// ---------------- stage B: gs/gis from g0; ws from weight ----------------
__global__ void k_prep(const float* __restrict__ W) {
    __shared__ float sm[2 * 2160];
    int w = threadIdx.x >> 5, lane = threadIdx.x & 31;
    float* sA  = sm + w * 2160;
    float* sV  = sA + 1056;
    float2* sCS2 = reinterpret_cast<float2*>(sV + 1056);
    const float* src = (w == 0) ? d_g0 : W;
    #pragma unroll
    for (int i = 0; i < 32; i++) sA[i * 33 + lane] = src[i * 32 + lane];
    __syncwarp();
    warp_eigh32(sA, sV, sCS2, lane, 1e-10f, 1e-9f);
    if (w == 0) {
        warp_matfn(sA, sV, (float*)sCS2, d_gs,  32, lane, FnSqrt());
        warp_matfn(sA, sV, (float*)sCS2, d_gis, 32, lane, FnRsqrt());
    } else {
        warp_matfn(sA, sV, (float*)sCS2, d_ws,  32, lane, FnSqrt());
    }
}

// ---------------- stage C: per-matrix logm(sym(gis X gis)), block-summed --
// Per-warp layout: sA33[1056] | sP[1024 packed] | sCS2[32] | sLam[32]
// gis_p[1024 packed] is block-shared at offset 0.
__global__ __launch_bounds__(256, 3) void k_logmean(const float* __restrict__ X) {
    extern __shared__ float sm[];
    float* gis_p = sm;                                  // packed stride-32
    int tid = threadIdx.x, w = tid >> 5, lane = tid & 31;
    for (int e = tid; e < NEL; e += 256) gis_p[e] = d_gis[e];
    __syncthreads();

    float* warpb = sm + 1024 + w * LM_WARP_FLOATS;
    float* sA    = warpb;                               // 1056 (stride 33)
    float* sP    = warpb + 1056;                        // 1024 (stride 32)
    float2* sCS2 = reinterpret_cast<float2*>(warpb + 2080);
    float* sLam  = warpb + 2112;

    size_t m = (size_t)blockIdx.x * LM_WPB + w;
    const float* xp = X + m * NEL;

    // stage X packed into sP (float4 all the way)
    {
        const float4* xp4 = reinterpret_cast<const float4*>(xp);
        float4* sP4 = reinterpret_cast<float4*>(sP);
        #pragma unroll
        for (int j = 0; j < 8; j++) sP4[j * 32 + lane] = xp4[j * 32 + lane];
    }
    __syncwarp();

    // ---- congruence: U = X*gis (into sA), M = gis*U (into sA) ----
    {
        float gcol[32];
        #pragma unroll
        for (int l = 0; l < 32; l++) gcol[l] = gis_p[l * 32 + lane]; // gis[:,lane]
        #pragma unroll
        for (int i = 0; i < 32; i++) {
            const float4* xr = reinterpret_cast<const float4*>(sP + i * 32);
            float acc = 0.f;
            #pragma unroll
            for (int j = 0; j < 8; j++) {
                float4 x4 = xr[j];
                acc += x4.x * gcol[4*j]   + x4.y * gcol[4*j+1]
                     + x4.z * gcol[4*j+2] + x4.w * gcol[4*j+3];
            }
            sA[i * 33 + lane] = acc;                    // U[i][lane]
        }
        __syncwarp();
        float ucol[32];
        #pragma unroll
        for (int l = 0; l < 32; l++) ucol[l] = sA[l * 33 + lane];   // U[:,lane]
        __syncwarp();
        #pragma unroll
        for (int i = 0; i < 32; i++) {
            const float4* gr = reinterpret_cast<const float4*>(gis_p + i * 32);
            float acc = 0.f;
            #pragma unroll
            for (int j = 0; j < 8; j++) {
                float4 g4 = gr[j];
                acc += g4.x * ucol[4*j]   + g4.y * ucol[4*j+1]
                     + g4.z * ucol[4*j+2] + g4.w * ucol[4*j+3];
            }
            sA[i * 33 + lane] = acc;                    // M[i][lane]
        }
        __syncwarp();
    }
    // symmetrize (pairwise per lane; matches reference _sym)
    for (int i = 0; i < lane; i++) {
        float a = sA[i * 33 + lane], b = sA[lane * 33 + i];
        float h = 0.5f * (a + b);
        sA[i * 33 + lane] = h; sA[lane * 33 + i] = h;
    }
    __syncwarp();

    // eigensolve; V^T written packed into sP (X no longer needed)
    warp_eigh32_bl(sA, sP, sCS2, lane, 1e-6f, 1e-6f);

    // ---- matfn: logm = V diag(log lam) V^T, using packed V^T ----
    {
        sLam[lane] = logf(fmaxf(sA[lane * 33 + lane], 1e-30f));
        __syncwarp();
        float vj[32];
        #pragma unroll
        for (int k = 0; k < 32; k++) vj[k] = sP[k * 32 + lane] * sLam[k];
        __syncwarp();
        #pragma unroll
        for (int ib = 0; ib < 8; ib++) {
            float a0 = 0.f, a1 = 0.f, a2 = 0.f, a3 = 0.f;
            #pragma unroll
            for (int k = 0; k < 32; k++) {
                float4 v4 = *reinterpret_cast<const float4*>(sP + k * 32 + ib * 4);
                a0 += v4.x * vj[k]; a1 += v4.y * vj[k];
                a2 += v4.z * vj[k]; a3 += v4.w * vj[k];
            }
            sA[(ib * 4 + 0) * 33 + lane] = a0;
            sA[(ib * 4 + 1) * 33 + lane] = a1;
            sA[(ib * 4 + 2) * 33 + lane] = a2;
            sA[(ib * 4 + 3) * 33 + lane] = a3;
        }
        __syncwarp();
    }

    __syncthreads();
    // deterministic fixed-order block reduction over the 8 warp buffers
    float* outp = d_partT + (size_t)blockIdx.x * NEL;
    for (int e = tid; e < NEL; e += 256) {
        int i = e >> 5, j = e & 31;
        float s = 0.f;
        #pragma unroll
        for (int ww = 0; ww < LM_WPB; ww++)
            s += sm[1024 + ww * LM_WARP_FLOATS + i * 33 + j];
        outp[e] = s;
    }
}

__global__ void k_redT1() {
    int b = blockIdx.x, e = threadIdx.x;
    float s = 0.f;
    for (int i = 0; i < LM_BLOCKS / 64; i++)
        s += d_partT[((size_t)(b * (LM_BLOCKS / 64) + i)) * NEL + e];
    d_partT2[b * NEL + e] = s;
}

__global__ void k_redT2() {
    int e = threadIdx.x;
    float s = 0.f;
    for (int b = 0; b < 64; b++) s += d_partT2[b * NEL + e];
    d_t[e] = s * (1.0f / (float)NM);
}

// ---------------- stage D: Karcher update + final factor A_f --------------
__global__ void k_final() {
    __shared__ float sm[4 * 1056 + 48];
    float* sA  = sm;
    float* sV  = sm + 1056;
    float* sB  = sm + 2112;
    float* sC  = sm + 3168;
    float2* sCS2 = reinterpret_cast<float2*>(sm + 4224);
    int lane = threadIdx.x;

    // E = expm(t)
    #pragma unroll
    for (int i = 0; i < 32; i++) sA[i * 33 + lane] = d_t[i * 32 + lane];
    __syncwarp();
    warp_eigh32(sA, sV, sCS2, lane, 1e-10f, 1e-9f);
    warp_matfn(sA, sV, (float*)sCS2, sB, 33, lane, FnExp());   // sB = E

    // g = sym(gs * E * gs)
    #pragma unroll
    for (int i = 0; i < 32; i++) sC[i * 33 + lane] = d_gs[i * 32 + lane];
    __syncwarp();
    warp_mm(sA, sC, sB, lane);                        // sA = gs*E
    warp_mm(sV, sA, sC, lane);                        // sV = gs*E*gs
    for (int i = 0; i < lane; i++) {
        float a = sV[i * 33 + lane], b = sV[lane * 33 + i];
        float h = 0.5f * (a + b);
        sV[i * 33 + lane] = h; sV[lane * 33 + i] = h;
    }
    __syncwarp();

    // gis2 = invsqrtm(g)
    warp_eigh32(sV, sB, sCS2, lane, 1e-10f, 1e-9f);   // matrix in sV, vectors in sB
    warp_matfn(sV, sB, (float*)sCS2, sA, 33, lane, FnRsqrt()); // sA = gis2

    // A_f = ws * gis2
    #pragma unroll
    for (int i = 0; i < 32; i++) sC[i * 33 + lane] = d_ws[i * 32 + lane];
    __syncwarp();
    warp_mm(sB, sC, sA, lane);                        // sB = ws*gis2
    #pragma unroll
    for (int i = 0; i < 32; i++) d_Af[i * 32 + lane] = sB[i * 33 + lane];
}

// ---------------- stage E: out = A_f * X * A_f^T per matrix ---------------
// smem: A_p[1024 packed] | A33[1056 padded] | per-warp T[1024 packed]
__global__ __launch_bounds__(256, 4) void k_apply(const float* __restrict__ X,
                                                  float* __restrict__ out) {
    extern __shared__ float sm[];
    float* A_p  = sm;            // packed, for float4 broadcast reads
    float* A33  = sm + 1024;     // padded, for per-lane row reads
    int tid = threadIdx.x, w = tid >> 5, lane = tid & 31;
    for (int e = tid; e < NEL; e += 256) {
        float v = d_Af[e];
        A_p[e] = v;
        A33[(e >> 5) * 33 + (e & 31)] = v;
    }
    __syncthreads();

    float* T = sm + 2080 + w * 1024;   // per-warp packed T buffer
    size_t m = (size_t)blockIdx.x * LM_WPB + w;
    const float* xp = X + m * NEL;

    float xcol[32];
    #pragma unroll
    for (int i = 0; i < 32; i++) xcol[i] = xp[i * 32 + lane];   // X[:,lane]

    // T = A * X  (A rows via float4 broadcast)
    #pragma unroll
    for (int i = 0; i < 32; i++) {
        const float4* ar = reinterpret_cast<const float4*>(A_p + i * 32);
        float acc = 0.f;
        #pragma unroll
        for (int j = 0; j < 8; j++) {
            float4 a4 = ar[j];
            acc += a4.x * xcol[4*j]   + a4.y * xcol[4*j+1]
                 + a4.z * xcol[4*j+2] + a4.w * xcol[4*j+3];
        }
        T[i * 32 + lane] = acc;        // bank = lane, conflict-free
    }
    __syncwarp();

    // Y[i][lane] = sum_l T[i][l] * A[lane][l]
    float arow[32];
    #pragma unroll
    for (int l = 0; l < 32; l++) arow[l] = A33[lane * 33 + l];
    float* op = out + m * NEL;
    #pragma unroll
    for (int i = 0; i < 32; i++) {
        const float4* tr = reinterpret_cast<const float4*>(T + i * 32);
        float acc = 0.f;
        #pragma unroll
        for (int j = 0; j < 8; j++) {
            float4 t4 = tr[j];
            acc += t4.x * arow[4*j]   + t4.y * arow[4*j+1]
                 + t4.z * arow[4*j+2] + t4.w * arow[4*j+3];
        }
        op[i * 32 + lane] = acc;
    }
}

// ---------------- launch ----------------
extern "C" void kernel_launch(void* const* d_in, const int* in_sizes, int n_in,
                              void* d_out, int out_size) {
    (void)in_sizes; (void)n_in; (void)out_size;
    const float* X = (const float*)d_in[0];
    const float* W = (const float*)d_in[1];
    float* out = (float*)d_out;

    const int LM_SMEM = LM_SMEM_FLOATS * 4;             // 72,704 B
    const int AP_SMEM = (2080 + LM_WPB * 1024) * 4;     // 41,088 B
    cudaFuncSetAttribute(k_logmean, cudaFuncAttributeMaxDynamicSharedMemorySize, LM_SMEM);
    cudaFuncSetAttribute(k_apply,   cudaFuncAttributeMaxDynamicSharedMemorySize, AP_SMEM);

    k_sumA<<<256, 256>>>(X);
    k_redA<<<4, 256>>>();
    k_prep<<<1, 64>>>(W);
    k_logmean<<<LM_BLOCKS, 256, LM_SMEM>>>(X);
    k_redT1<<<64, 1024>>>();
    k_redT2<<<1, 1024>>>();
    k_final<<<1, 32>>>();
    k_apply<<<LM_BLOCKS, 256, AP_SMEM>>>(X, out);
}

// round 17
// speedup vs baseline: 1.0675x; 1.0675x over previous
#include <cuda_runtime.h>
#include <cuda_bf16.h>
#include <math.h>

// Problem shape (fixed by dataset): X [2048,16,32,32] f32, weight [32,32] f32.
#define NM      32768          // 2048*16 matrices
#define NEL     1024           // 32*32
#define LM_WPB  8              // warps (matrices) per block in heavy kernels
#define LM_BLOCKS (NM / LM_WPB)  // 4096

// ---------------- device scratch (static, no allocation) ----------------
__device__ float d_partA[256 * NEL];        // stage-A block partials
__device__ float d_g0[NEL];                 // arithmetic mean of X
__device__ float d_gs[NEL];                 // sqrtm(g0)
__device__ float d_gis[NEL];                // invsqrtm(g0)
__device__ float d_ws[NEL];                 // sqrtm(weight)
__device__ float d_partT[LM_BLOCKS * NEL];  // per-block logm partial sums (16 MB)
__device__ float d_partT2[64 * NEL];        // second-level partials
__device__ float d_t[NEL];                  // mean of logms
__device__ float d_Af[NEL];                 // final congruence factor ws*gis2

// ---------------- small helpers ----------------
__device__ __forceinline__ void get_pq(int r, int k, int& p, int& q) {
    if (k == 0) { p = 31; q = r; }
    else {
        p = r + k; if (p >= 31) p -= 31;
        q = r - k; if (q < 0)  q += 31;
    }
}

// Compute the 16 disjoint rotations for round r (lanes 0-15), store (c,s)
// pairs as float2. Branchless: skip folds to (1,0), bitwise-identical update.
__device__ __forceinline__ void jacobi_phase1(const float* sA, float2* sCS2,
                                              int lane, int r, float skip,
                                              float& off) {
    if (lane < 16) {
        int p, q; get_pq(r, lane, p, q);
        float app = sA[p * 33 + p];
        float aqq = sA[q * 33 + q];
        float apq = sA[p * 33 + q];
        off += apq * apq;
        bool g = fabsf(apq) > skip * (fabsf(app) + fabsf(aqq) + 1e-30f);
        float den = g ? apq : 1.0f;
        float theta = 0.5f * (aqq - app) / den;
        float tt = 1.0f / (fabsf(theta) + sqrtf(1.0f + theta * theta));
        tt = copysignf(tt, theta);
        float c = rsqrtf(1.0f + tt * tt);
        float s = tt * c;
        sCS2[lane] = make_float2(g ? c : 1.0f, g ? s : 0.0f);
    }
}

// =====================================================================
// Brent-Luk Jacobi (used by ALL paths now). V row lives in registers,
// indexed by CIRCLE POSITION, so register indices are static in a ROLLED
// round loop (small I$ body). Schedule: player p=(r+k)%31 sits at position
// k, player q=(r-k)%31 at position 31-k; player 31 is the fixed center.
// After each round positions shift by one; after 31 rounds (sweep
// boundary) the seating is identity, so exit needs no reindexing.
// A stays in smem (natural order, dynamic indices). Writes V rows to
// padded sV (stride 33). Bitwise-identical to the original smem solver.
// =====================================================================
__device__ void warp_eigh32_bl(float* sA, float* sV, float2* sCS2, int lane,
                               float tol, float skip) {
    float* rowA = sA + lane * 33;
    float* colA = sA + lane;

    float vp[31], vc;
    #pragma unroll
    for (int j = 0; j < 31; j++) vp[j] = (j == lane) ? 1.0f : 0.0f;
    vc = (lane == 31) ? 1.0f : 0.0f;
    __syncwarp();

    #pragma unroll 1
    for (int sweep = 0; sweep < 10; sweep++) {
        float off = 0.0f;
        #pragma unroll 1
        for (int r = 0; r < 31; r++) {
            jacobi_phase1(sA, sCS2, lane, r, skip, off);
            __syncwarp();
            {   // k = 0: players (31, r) -> registers (vc, vp[0])
                float2 cs = sCS2[0];
                float x = rowA[31], y = rowA[r];
                rowA[31] = cs.x * x - cs.y * y;
                rowA[r]  = cs.y * x + cs.x * y;
                float vx = vc, vy = vp[0];
                vc    = cs.x * vx - cs.y * vy;
                vp[0] = cs.y * vx + cs.x * vy;
            }
            #pragma unroll
            for (int k = 1; k < 16; k++) {
                float2 cs = sCS2[k];
                int p = r + k; if (p >= 31) p -= 31;
                int q = r - k; if (q < 0)  q += 31;
                float x = rowA[p], y = rowA[q];
                rowA[p] = cs.x * x - cs.y * y;
                rowA[q] = cs.y * x + cs.x * y;
                float vx = vp[k], vy = vp[31 - k];
                vp[k]      = cs.x * vx - cs.y * vy;
                vp[31 - k] = cs.y * vx + cs.x * vy;
            }
            __syncwarp();
            {
                float2 cs = sCS2[0];
                float x = colA[31 * 33], y = colA[r * 33];
                colA[31 * 33] = cs.x * x - cs.y * y;
                colA[r * 33]  = cs.y * x + cs.x * y;
            }
            #pragma unroll
            for (int k = 1; k < 16; k++) {
                float2 cs = sCS2[k];
                int p = r + k; if (p >= 31) p -= 31;
                int q = r - k; if (q < 0)  q += 31;
                float x = colA[p * 33], y = colA[q * 33];
                colA[p * 33] = cs.x * x - cs.y * y;
                colA[q * 33] = cs.y * x + cs.x * y;
            }
            __syncwarp();
            // advance seating: player at pos j moves to pos j-1
            float t0 = vp[0];
            #pragma unroll
            for (int j = 0; j < 30; j++) vp[j] = vp[j + 1];
            vp[30] = t0;
        }
        float dd  = rowA[lane];
        float dsq = dd * dd;
        #pragma unroll
        for (int o = 16; o > 0; o >>= 1) {
            off += __shfl_xor_sync(0xffffffffu, off, o);
            dsq += __shfl_xor_sync(0xffffffffu, dsq, o);
        }
        if (off <= tol * dsq) break;
    }
    // sweep boundary: seating is identity -> direct padded writeback
    float* rowV = sV + lane * 33;
    #pragma unroll
    for (int j = 0; j < 31; j++) rowV[j] = vp[j];
    rowV[31] = vc;
    __syncwarp();
}

struct FnLog   { __device__ float operator()(float x) const { return logf(fmaxf(x, 1e-30f)); } };
struct FnExp   { __device__ float operator()(float x) const { return expf(x); } };
struct FnSqrt  { __device__ float operator()(float x) const { return sqrtf(fmaxf(x, 0.0f)); } };
struct FnRsqrt { __device__ float operator()(float x) const { return rsqrtf(fmaxf(x, 1e-30f)); } };

// out[i][j] = sum_k V[i][k] f(lambda_k) V[j][k].
// out may alias sA (diag consumed into sTmp first); out must NOT alias sV.
template <class F>
__device__ void warp_matfn(const float* sA, const float* sV, float* sTmp,
                           float* out, int ostride, int lane, F f) {
    sTmp[lane] = f(sA[lane * 33 + lane]);
    __syncwarp();
    float vj[32];                     // vj[k] = V[lane][k] * f(lambda_k)
    #pragma unroll
    for (int k = 0; k < 32; k++) vj[k] = sV[lane * 33 + k] * sTmp[k];
    __syncwarp();
    #pragma unroll
    for (int i = 0; i < 32; i++) {
        float acc = 0.0f;
        #pragma unroll
        for (int k = 0; k < 32; k++) acc += sV[i * 33 + k] * vj[k];
        out[i * ostride + lane] = acc;
    }
    __syncwarp();
}

// C = A * B (all 32x32, pad-33 smem). C must not alias A or B.
__device__ void warp_mm(float* C, const float* A, const float* B, int lane) {
    float bcol[32];
    #pragma unroll
    for (int l = 0; l < 32; l++) bcol[l] = B[l * 33 + lane];
    #pragma unroll
    for (int i = 0; i < 32; i++) {
        float acc = 0.0f;
        #pragma unroll
        for (int l = 0; l < 32; l++) acc += A[i * 33 + l] * bcol[l];
        C[i * 33 + lane] = acc;
    }
    __syncwarp();
}

// ---------------- stage A: arithmetic mean of all matrices ----------------
__global__ void k_sumA(const float* __restrict__ X) {
    int b = blockIdx.x, t = threadIdx.x;
    const int MPB = NM / 256;   // 128 matrices per block
    const float* base = X + (size_t)b * MPB * NEL;
    float a0 = 0.f, a1 = 0.f, a2 = 0.f, a3 = 0.f;
    for (int m = 0; m < MPB; m++) {
        const float* p = base + (size_t)m * NEL;
        a0 += p[t];        a1 += p[t + 256];
        a2 += p[t + 512];  a3 += p[t + 768];
    }
    d_partA[b * NEL + t]       = a0;
    d_partA[b * NEL + t + 256] = a1;
    d_partA[b * NEL + t + 512] = a2;
    d_partA[b * NEL + t + 768] = a3;
}

__global__ void k_redA() {
    int e = blockIdx.x * 256 + threadIdx.x;
    float s = 0.f;
    #pragma unroll 8
    for (int b = 0; b < 256; b++) s += d_partA[b * NEL + e];
    d_g0[e] = s * (1.0f / (float)NM);
}

// ---------------- stage B: gs/gis from g0; ws from weight ----------------
__global__ void k_prep(const float* __restrict__ W) {
    __shared__ float sm[2 * 2160];
    int w = threadIdx.x >> 5, lane = threadIdx.x & 31;
    float* sA  = sm + w * 2160;
    float* sV  = sA + 1056;
    float2* sCS2 = reinterpret_cast<float2*>(sV + 1056);
    const float* src = (w == 0) ? d_g0 : W;
    #pragma unroll
    for (int i = 0; i < 32; i++) sA[i * 33 + lane] = src[i * 32 + lane];
    __syncwarp();
    warp_eigh32_bl(sA, sV, sCS2, lane, 1e-10f, 1e-9f);
    if (w == 0) {
        warp_matfn(sA, sV, (float*)sCS2, d_gs,  32, lane, FnSqrt());
        warp_matfn(sA, sV, (float*)sCS2, d_gis, 32, lane, FnRsqrt());
    } else {
        warp_matfn(sA, sV, (float*)sCS2, d_ws,  32, lane, FnSqrt());
    }
}

// ---------------- stage C: per-matrix logm(sym(gis X gis)), block-summed --
__global__ __launch_bounds__(256, 3) void k_logmean(const float* __restrict__ X) {
    extern __shared__ float sm[];
    float* gis_s = sm;                                  // 1056
    int tid = threadIdx.x, w = tid >> 5, lane = tid & 31;
    for (int e = tid; e < NEL; e += 256)
        gis_s[(e >> 5) * 33 + (e & 31)] = d_gis[e];
    __syncthreads();

    float* sA  = sm + 1056 + w * 2160;
    float* sV  = sA + 1056;
    float2* sCS2 = reinterpret_cast<float2*>(sV + 1056); // 32 floats

    size_t m = (size_t)blockIdx.x * LM_WPB + w;
    const float* xp = X + m * NEL;
    #pragma unroll
    for (int i = 0; i < 32; i++) sA[i * 33 + lane] = xp[i * 32 + lane];
    __syncwarp();

    // Low-register congruence: U = X*gis into sV, then M = gis*U into sA.
    {
        float col[32];
        #pragma unroll
        for (int l = 0; l < 32; l++) col[l] = gis_s[l * 33 + lane];  // gis[:,lane]
        #pragma unroll
        for (int i = 0; i < 32; i++) {
            float acc = 0.f;
            #pragma unroll
            for (int l = 0; l < 32; l++) acc += sA[i * 33 + l] * col[l];
            sV[i * 33 + lane] = acc;                                  // U[i][lane]
        }
        __syncwarp();
        #pragma unroll
        for (int l = 0; l < 32; l++) col[l] = sV[l * 33 + lane];      // U[:,lane]
        __syncwarp();
        #pragma unroll
        for (int i = 0; i < 32; i++) {
            float acc = 0.f;
            #pragma unroll
            for (int l = 0; l < 32; l++) acc += gis_s[i * 33 + l] * col[l];
            sA[i * 33 + lane] = acc;                                  // M[i][lane]
        }
        __syncwarp();
    }
    // symmetrize (matches reference _sym)
    for (int i = 0; i < lane; i++) {
        float a = sA[i * 33 + lane], b = sA[lane * 33 + i];
        float h = 0.5f * (a + b);
        sA[i * 33 + lane] = h; sA[lane * 33 + i] = h;
    }
    __syncwarp();

    warp_eigh32_bl(sA, sV, sCS2, lane, 1e-6f, 1e-6f);
    warp_matfn(sA, sV, (float*)sCS2, sA, 33, lane, FnLog());   // sA = logm(M)

    __syncthreads();
    // deterministic fixed-order block reduction over the 8 warp buffers
    float* outp = d_partT + (size_t)blockIdx.x * NEL;
    for (int e = tid; e < NEL; e += 256) {
        int i = e >> 5, j = e & 31;
        float s = 0.f;
        #pragma unroll
        for (int ww = 0; ww < LM_WPB; ww++)
            s += sm[1056 + ww * 2160 + i * 33 + j];
        outp[e] = s;
    }
}

__global__ void k_redT1() {
    int b = blockIdx.x, e = threadIdx.x;
    float s = 0.f;
    for (int i = 0; i < LM_BLOCKS / 64; i++)
        s += d_partT[((size_t)(b * (LM_BLOCKS / 64) + i)) * NEL + e];
    d_partT2[b * NEL + e] = s;
}

__global__ void k_redT2() {
    int e = threadIdx.x;
    float s = 0.f;
    for (int b = 0; b < 64; b++) s += d_partT2[b * NEL + e];
    d_t[e] = s * (1.0f / (float)NM);
}

// ---------------- stage D: Karcher update + final factor A_f --------------
__global__ void k_final() {
    __shared__ float sm[4 * 1056 + 48];
    float* sA  = sm;
    float* sV  = sm + 1056;
    float* sB  = sm + 2112;
    float* sC  = sm + 3168;
    float2* sCS2 = reinterpret_cast<float2*>(sm + 4224);
    int lane = threadIdx.x;

    // E = expm(t)
    #pragma unroll
    for (int i = 0; i < 32; i++) sA[i * 33 + lane] = d_t[i * 32 + lane];
    __syncwarp();
    warp_eigh32_bl(sA, sV, sCS2, lane, 1e-10f, 1e-9f);
    warp_matfn(sA, sV, (float*)sCS2, sB, 33, lane, FnExp());   // sB = E

    // g = sym(gs * E * gs)
    #pragma unroll
    for (int i = 0; i < 32; i++) sC[i * 33 + lane] = d_gs[i * 32 + lane];
    __syncwarp();
    warp_mm(sA, sC, sB, lane);                        // sA = gs*E
    warp_mm(sV, sA, sC, lane);                        // sV = gs*E*gs
    for (int i = 0; i < lane; i++) {
        float a = sV[i * 33 + lane], b = sV[lane * 33 + i];
        float h = 0.5f * (a + b);
        sV[i * 33 + lane] = h; sV[lane * 33 + i] = h;
    }
    __syncwarp();

    // gis2 = invsqrtm(g)
    warp_eigh32_bl(sV, sB, sCS2, lane, 1e-10f, 1e-9f); // matrix in sV, vectors in sB
    warp_matfn(sV, sB, (float*)sCS2, sA, 33, lane, FnRsqrt()); // sA = gis2

    // A_f = ws * gis2
    #pragma unroll
    for (int i = 0; i < 32; i++) sC[i * 33 + lane] = d_ws[i * 32 + lane];
    __syncwarp();
    warp_mm(sB, sC, sA, lane);                        // sB = ws*gis2
    #pragma unroll
    for (int i = 0; i < 32; i++) d_Af[i * 32 + lane] = sB[i * 33 + lane];
}

// ---------------- stage E: out = A_f * X * A_f^T per matrix ---------------
// smem: A_p[1024 packed] | A33[1056 padded] | per-warp T[1024 packed]
// float4 broadcast loads with STRICTLY ORDERED fmaf chains -> accumulation
// order identical to the scalar version (bitwise-identical output).
__global__ __launch_bounds__(256, 4) void k_apply(const float* __restrict__ X,
                                                  float* __restrict__ out) {
    extern __shared__ float sm[];
    float* A_p  = sm;            // packed, for float4 broadcast reads
    float* A33  = sm + 1024;     // padded, for per-lane row reads
    int tid = threadIdx.x, w = tid >> 5, lane = tid & 31;
    for (int e = tid; e < NEL; e += 256) {
        float v = d_Af[e];
        A_p[e] = v;
        A33[(e >> 5) * 33 + (e & 31)] = v;
    }
    __syncthreads();

    float* T = sm + 2080 + w * 1024;   // per-warp packed T buffer
    size_t m = (size_t)blockIdx.x * LM_WPB + w;
    const float* xp = X + m * NEL;

    float xcol[32];
    #pragma unroll
    for (int i = 0; i < 32; i++) xcol[i] = xp[i * 32 + lane];   // X[:,lane]

    // T = A * X  (A rows via float4 broadcast; ordered fmaf chain)
    #pragma unroll
    for (int i = 0; i < 32; i++) {
        const float4* ar = reinterpret_cast<const float4*>(A_p + i * 32);
        float acc = 0.f;
        #pragma unroll
        for (int j = 0; j < 8; j++) {
            float4 a4 = ar[j];
            acc = fmaf(a4.x, xcol[4*j],     acc);
            acc = fmaf(a4.y, xcol[4*j + 1], acc);
            acc = fmaf(a4.z, xcol[4*j + 2], acc);
            acc = fmaf(a4.w, xcol[4*j + 3], acc);
        }
        T[i * 32 + lane] = acc;        // bank = lane, conflict-free
    }
    __syncwarp();

    // Y[i][lane] = sum_l T[i][l] * A[lane][l]
    float arow[32];
    #pragma unroll
    for (int l = 0; l < 32; l++) arow[l] = A33[lane * 33 + l];
    float* op = out + m * NEL;
    #pragma unroll
    for (int i = 0; i < 32; i++) {
        const float4* tr = reinterpret_cast<const float4*>(T + i * 32);
        float acc = 0.f;
        #pragma unroll
        for (int j = 0; j < 8; j++) {
            float4 t4 = tr[j];
            acc = fmaf(t4.x, arow[4*j],     acc);
            acc = fmaf(t4.y, arow[4*j + 1], acc);
            acc = fmaf(t4.z, arow[4*j + 2], acc);
            acc = fmaf(t4.w, arow[4*j + 3], acc);
        }
        op[i * 32 + lane] = acc;
    }
}

// ---------------- launch ----------------
extern "C" void kernel_launch(void* const* d_in, const int* in_sizes, int n_in,
                              void* d_out, int out_size) {
    (void)in_sizes; (void)n_in; (void)out_size;
    const float* X = (const float*)d_in[0];
    const float* W = (const float*)d_in[1];
    float* out = (float*)d_out;

    const int LM_SMEM = (1056 + LM_WPB * 2160) * 4;   // 73,344 B
    const int AP_SMEM = (2080 + LM_WPB * 1024) * 4;   // 41,088 B
    cudaFuncSetAttribute(k_logmean, cudaFuncAttributeMaxDynamicSharedMemorySize, LM_SMEM);
    cudaFuncSetAttribute(k_apply,   cudaFuncAttributeMaxDynamicSharedMemorySize, AP_SMEM);

    k_sumA<<<256, 256>>>(X);
    k_redA<<<4, 256>>>();
    k_prep<<<1, 64>>>(W);
    k_logmean<<<LM_BLOCKS, 256, LM_SMEM>>>(X);
    k_redT1<<<64, 1024>>>();
    k_redT2<<<1, 1024>>>();
    k_final<<<1, 32>>>();
    k_apply<<<LM_BLOCKS, 256, AP_SMEM>>>(X, out);
}